// round 7
// baseline (speedup 1.0000x reference)
#include <cuda_runtime.h>

#define FM_H 38
#define FM_W 50
#define N_ROI 512
#define POOL 7

__device__ __forceinline__ float4 quad4(float4 a, float4 b, float4 c, float4 d,
                                        float w0, float w1, float w2, float w3) {
    float4 r;
    r.x = fmaf(d.x, w3, fmaf(c.x, w2, fmaf(b.x, w1, a.x * w0)));
    r.y = fmaf(d.y, w3, fmaf(c.y, w2, fmaf(b.y, w1, a.y * w0)));
    r.z = fmaf(d.z, w3, fmaf(c.z, w2, fmaf(b.z, w1, a.z * w0)));
    r.w = fmaf(d.w, w3, fmaf(c.w, w2, fmaf(b.w, w1, a.w * w0)));
    return r;
}

__device__ __forceinline__ float4 max4(float4 a, float4 b) {
    float4 r;
    r.x = fmaxf(a.x, b.x);
    r.y = fmaxf(a.y, b.y);
    r.z = fmaxf(a.z, b.z);
    r.w = fmaxf(a.w, b.w);
    return r;
}

__device__ __forceinline__ float4 sel4(bool p, float4 a, float4 b) {
    float4 r;
    r.x = p ? a.x : b.x;
    r.y = p ? a.y : b.y;
    r.z = p ? a.z : b.z;
    r.w = p ? a.w : b.w;
    return r;
}

// Streams the 7 pooled cells of one pooled row. Row set (NR rows, pair-b
// starts at row PB) fixed per block. K0: all cells' x-taps fit in 3
// contiguous columns (small-ROI class, block-uniform) -> 3 column loads
// per row + branch-free selects for pair-b; else 4 column loads (R5 path).
// Both variants are straight-line across all 7 cells (no per-cell branches).
template <int NR, int PB, bool K0>
__device__ __forceinline__ void run_row(
    const float4* __restrict__ fmt, float4* __restrict__ outp,
    float x1n, float dx,
    int r0, int r1, int r2, int r3,
    float waP, float waQ, float wbP, float wbQ)
{
    int ro[4] = {r0, r1, r2, r3};

#pragma unroll
    for (int px = 0; px < POOL; ++px) {
        int x0a, x1a, x0b, x1b;
        float wxa, wxb;
        {
            const float txa = (float)(2 * px) * (1.0f / 13.0f);
            const float xsa = (x1n + txa * dx) * (float)(FM_W - 1);
            const float xfa = floorf(xsa);
            int x0 = (int)xfa; x0 = min(max(x0, 0), FM_W - 1);
            x0a = x0; x1a = min(x0 + 1, FM_W - 1); wxa = xsa - xfa;

            const float txb = (float)(2 * px + 1) * (1.0f / 13.0f);
            const float xsb = (x1n + txb * dx) * (float)(FM_W - 1);
            const float xfb = floorf(xsb);
            int x1 = (int)xfb; x1 = min(max(x1, 0), FM_W - 1);
            x0b = x1; x1b = min(x1 + 1, FM_W - 1); wxb = xsb - xfb;
        }
        const float uxa = 1.0f - wxa;
        const float uxb = 1.0f - wxb;

        float4 s_aa, s_ab, s_ba, s_bb;

        if (K0) {
            // 3 contiguous columns cover all taps: {x0a, x1a, x2c}
            const int x2c = min(x0a + 2, FM_W - 1);
            float4 G0[NR], G1[NR], G2[NR];
#pragma unroll
            for (int r = 0; r < NR; ++r) {
                G0[r] = fmt[(ro[r] + x0a) * 128];
                G1[r] = fmt[(ro[r] + x1a) * 128];
                G2[r] = fmt[(ro[r] + x2c) * 128];
            }
            // pair-b columns: off==1 -> (G1,G2), off==0 -> (G0,G1)
            const bool hi = (x0b != x0a);
            const float4 bP0 = sel4(hi, G1[PB],     G0[PB]);
            const float4 bP1 = sel4(hi, G2[PB],     G1[PB]);
            const float4 bQ0 = sel4(hi, G1[PB + 1], G0[PB + 1]);
            const float4 bQ1 = sel4(hi, G2[PB + 1], G1[PB + 1]);

            s_aa = quad4(G0[0],  G1[0],  G0[1],      G1[1],
                         waP * uxa, waP * wxa, waQ * uxa, waQ * wxa);
            s_ab = quad4(sel4(hi, G1[0], G0[0]), sel4(hi, G2[0], G1[0]),
                         sel4(hi, G1[1], G0[1]), sel4(hi, G2[1], G1[1]),
                         waP * uxb, waP * wxb, waQ * uxb, waQ * wxb);
            s_ba = quad4(G0[PB], G1[PB], G0[PB + 1], G1[PB + 1],
                         wbP * uxa, wbP * wxa, wbQ * uxa, wbQ * wxa);
            s_bb = quad4(bP0, bP1, bQ0, bQ1,
                         wbP * uxb, wbP * wxb, wbQ * uxb, wbQ * wxb);
        } else {
            // 4 independent column loads per row (R5 path)
            float4 C0[NR], C1[NR], C2[NR], C3[NR];
#pragma unroll
            for (int r = 0; r < NR; ++r) {
                C0[r] = fmt[(ro[r] + x0a) * 128];
                C1[r] = fmt[(ro[r] + x1a) * 128];
                C2[r] = fmt[(ro[r] + x0b) * 128];
                C3[r] = fmt[(ro[r] + x1b) * 128];
            }
            s_aa = quad4(C0[0],  C1[0],  C0[1],      C1[1],
                         waP * uxa, waP * wxa, waQ * uxa, waQ * wxa);
            s_ab = quad4(C2[0],  C3[0],  C2[1],      C3[1],
                         waP * uxb, waP * wxb, waQ * uxb, waQ * wxb);
            s_ba = quad4(C0[PB], C1[PB], C0[PB + 1], C1[PB + 1],
                         wbP * uxa, wbP * wxa, wbQ * uxa, wbQ * wxa);
            s_bb = quad4(C2[PB], C3[PB], C2[PB + 1], C3[PB + 1],
                         wbP * uxb, wbP * wxb, wbQ * uxb, wbQ * wxb);
        }

        outp[px * 128] = max4(max4(s_aa, s_ab), max4(s_ba, s_bb));
    }
}

template <int NR, int PB>
__device__ __forceinline__ void run_row_dispatch(
    bool k0, const float4* __restrict__ fmt, float4* __restrict__ outp,
    float x1n, float dx, int r0, int r1, int r2, int r3,
    float waP, float waQ, float wbP, float wbQ)
{
    if (k0)
        run_row<NR, PB, true >(fmt, outp, x1n, dx, r0, r1, r2, r3,
                               waP, waQ, wbP, wbQ);
    else
        run_row<NR, PB, false>(fmt, outp, x1n, dx, r0, r1, r2, r3,
                               waP, waQ, wbP, wbQ);
}

// One block per (pooled_row, roi). 128 threads x float4 = 512 channels.
// Row-tap dedup (block-uniform 3-way) x column-class dedup (block-uniform
// 2-way). All dispatches happen ONCE per block; cell loop is branch-free.
__global__ __launch_bounds__(128) void roi_pool_kernel(
    const float* __restrict__ fm,     // [38,50,512]
    const float* __restrict__ rois,   // [512,5] (0, x1, y1, x2, y2)
    float* __restrict__ out)          // [512,7,7,512]
{
    const int py  = blockIdx.x;       // 0..6
    const int roi = blockIdx.y;       // 0..511
    const int t   = threadIdx.x;      // channel group: c = 4*t

    const float* r = rois + roi * 5;
    const float x1n = r[1] * (1.0f / 800.0f);
    const float y1n = r[2] * (1.0f / 600.0f);
    const float x2n = r[3] * (1.0f / 800.0f);
    const float y2n = r[4] * (1.0f / 600.0f);
    const float dy = y2n - y1n;
    const float dx = x2n - x1n;

    // y taps for the two crop rows of this pooled row (block-uniform)
    int ra0, ra1, rb0, rb1;           // fm row offsets (row * FM_W)
    float wya, wyb;
    {
        const float tya = (float)(2 * py) * (1.0f / 13.0f);
        const float ysa = (y1n + tya * dy) * (float)(FM_H - 1);
        const float yfa = floorf(ysa);
        int y0 = (int)yfa; y0 = min(max(y0, 0), FM_H - 1);
        ra0 = y0 * FM_W;
        ra1 = min(y0 + 1, FM_H - 1) * FM_W;
        wya = ysa - yfa;

        const float tyb = (float)(2 * py + 1) * (1.0f / 13.0f);
        const float ysb = (y1n + tyb * dy) * (float)(FM_H - 1);
        const float yfb = floorf(ysb);
        int y1 = (int)yfb; y1 = min(max(y1, 0), FM_H - 1);
        rb0 = y1 * FM_W;
        rb1 = min(y1 + 1, FM_H - 1) * FM_W;
        wyb = ysb - yfb;
    }
    const float uya = 1.0f - wya;
    const float uyb = 1.0f - wyb;

    // Column-class: do every cell's 4 x-taps fit in {x0a, x0a+1, x0a+2}?
    bool k0;
    {
        int m = 0;
#pragma unroll
        for (int px = 0; px < POOL; ++px) {
            const float txa = (float)(2 * px) * (1.0f / 13.0f);
            const float xsa = (x1n + txa * dx) * (float)(FM_W - 1);
            int x0 = (int)floorf(xsa); x0 = min(max(x0, 0), FM_W - 1);
            const float txb = (float)(2 * px + 1) * (1.0f / 13.0f);
            const float xsb = (x1n + txb * dx) * (float)(FM_W - 1);
            int x1 = (int)floorf(xsb); x1 = min(max(x1, 0), FM_W - 1);
            m = max(m, x1 - x0);
        }
        k0 = (m <= 1);
    }

    const float4* fmt = (const float4*)fm + t;
    float4* outp = (float4*)out + (size_t)((roi * POOL + py) * POOL) * 128 + t;

    // Row dedup dispatch (block-uniform, fixed for all 7 cells).
    if (rb0 == ra0) {
        run_row_dispatch<2, 0>(k0, fmt, outp, x1n, dx, ra0, ra1, 0, 0,
                               uya, wya, uyb, wyb);
    } else if (rb0 == ra1) {
        if (rb1 == rb0) {
            run_row_dispatch<2, 0>(k0, fmt, outp, x1n, dx, ra0, ra1, 0, 0,
                                   uya, wya, 0.0f, uyb + wyb);
        } else {
            run_row_dispatch<3, 1>(k0, fmt, outp, x1n, dx, ra0, ra1, rb1, 0,
                                   uya, wya, uyb, wyb);
        }
    } else {
        run_row_dispatch<4, 2>(k0, fmt, outp, x1n, dx, ra0, ra1, rb0, rb1,
                               uya, wya, uyb, wyb);
    }
}

extern "C" void kernel_launch(void* const* d_in, const int* in_sizes, int n_in,
                              void* d_out, int out_size)
{
    const float* fm   = (const float*)d_in[0];   // feature_maps [1,38,50,512]
    const float* rois = (const float*)d_in[1];   // [512,5]
    float* out = (float*)d_out;                  // [1,512,7,7,512]

    dim3 grid(POOL, N_ROI);
    roi_pool_kernel<<<grid, 128>>>(fm, rois, out);
}

// round 8
// speedup vs baseline: 1.3360x; 1.3360x over previous
#include <cuda_runtime.h>

#define FM_H 38
#define FM_W 50
#define N_ROI 512
#define POOL 7

__device__ __forceinline__ float4 quad4(float4 a, float4 b, float4 c, float4 d,
                                        float w0, float w1, float w2, float w3) {
    float4 r;
    r.x = fmaf(d.x, w3, fmaf(c.x, w2, fmaf(b.x, w1, a.x * w0)));
    r.y = fmaf(d.y, w3, fmaf(c.y, w2, fmaf(b.y, w1, a.y * w0)));
    r.z = fmaf(d.z, w3, fmaf(c.z, w2, fmaf(b.z, w1, a.z * w0)));
    r.w = fmaf(d.w, w3, fmaf(c.w, w2, fmaf(b.w, w1, a.w * w0)));
    return r;
}

__device__ __forceinline__ float4 max4(float4 a, float4 b) {
    float4 r;
    r.x = fmaxf(a.x, b.x);
    r.y = fmaxf(a.y, b.y);
    r.z = fmaxf(a.z, b.z);
    r.w = fmaxf(a.w, b.w);
    return r;
}

// MODE 0: 2 distinct fm rows (r0,r1). Pair-b reads rows (r0,r1) with folded
//         weights. MODE 1: 3 rows, pair-b reads (r1,r2). MODE 2: 4 rows,
//         pair-b reads (r2,r3). Straight-line across all 7 cells.
template <int MODE>
__device__ __forceinline__ void run_row(
    const float4* __restrict__ fmt, float4* __restrict__ outp,
    float x1n, float dx,
    int r0, int r1, int r2, int r3,
    float waP, float waQ,      // row weights for pair a (rows r0,r1)
    float wbP, float wbQ)      // row weights for pair b (rows per MODE)
{
#pragma unroll
    for (int px = 0; px < POOL; ++px) {
        // x taps for the two crop cols of this pooled cell (block-uniform)
        int x0a, x1a, x0b, x1b;
        float wxa, wxb;
        {
            const float txa = (float)(2 * px) * (1.0f / 13.0f);
            const float xsa = (x1n + txa * dx) * (float)(FM_W - 1);
            const float xfa = floorf(xsa);
            int x0 = (int)xfa; x0 = min(max(x0, 0), FM_W - 1);
            x0a = x0; x1a = min(x0 + 1, FM_W - 1); wxa = xsa - xfa;

            const float txb = (float)(2 * px + 1) * (1.0f / 13.0f);
            const float xsb = (x1n + txb * dx) * (float)(FM_W - 1);
            const float xfb = floorf(xsb);
            int x1 = (int)xfb; x1 = min(max(x1, 0), FM_W - 1);
            x0b = x1; x1b = min(x1 + 1, FM_W - 1); wxb = xsb - xfb;
        }
        const float uxa = 1.0f - wxa;
        const float uxb = 1.0f - wxb;

        // Unconditional batched loads: (2 + MODE distinct rows) x 4 cols
        const float4 vA0a = fmt[(r0 + x0a) * 128];
        const float4 vA1a = fmt[(r0 + x1a) * 128];
        const float4 vA0b = fmt[(r0 + x0b) * 128];
        const float4 vA1b = fmt[(r0 + x1b) * 128];
        const float4 vB0a = fmt[(r1 + x0a) * 128];
        const float4 vB1a = fmt[(r1 + x1a) * 128];
        const float4 vB0b = fmt[(r1 + x0b) * 128];
        const float4 vB1b = fmt[(r1 + x1b) * 128];

        float4 vC0a, vC1a, vC0b, vC1b;   // pair-b source row P
        float4 vD0a, vD1a, vD0b, vD1b;   // pair-b source row Q
        if (MODE == 0) {
            vC0a = vA0a; vC1a = vA1a; vC0b = vA0b; vC1b = vA1b;
            vD0a = vB0a; vD1a = vB1a; vD0b = vB0b; vD1b = vB1b;
        } else if (MODE == 1) {
            vC0a = vB0a; vC1a = vB1a; vC0b = vB0b; vC1b = vB1b;
            vD0a = fmt[(r2 + x0a) * 128];
            vD1a = fmt[(r2 + x1a) * 128];
            vD0b = fmt[(r2 + x0b) * 128];
            vD1b = fmt[(r2 + x1b) * 128];
        } else {
            vC0a = fmt[(r2 + x0a) * 128];
            vC1a = fmt[(r2 + x1a) * 128];
            vC0b = fmt[(r2 + x0b) * 128];
            vC1b = fmt[(r2 + x1b) * 128];
            vD0a = fmt[(r3 + x0a) * 128];
            vD1a = fmt[(r3 + x1a) * 128];
            vD0b = fmt[(r3 + x0b) * 128];
            vD1b = fmt[(r3 + x1b) * 128];
        }

        const float4 s_aa = quad4(vA0a, vA1a, vB0a, vB1a,
                                  waP * uxa, waP * wxa, waQ * uxa, waQ * wxa);
        const float4 s_ab = quad4(vA0b, vA1b, vB0b, vB1b,
                                  waP * uxb, waP * wxb, waQ * uxb, waQ * wxb);
        const float4 s_ba = quad4(vC0a, vC1a, vD0a, vD1a,
                                  wbP * uxa, wbP * wxa, wbQ * uxa, wbQ * wxa);
        const float4 s_bb = quad4(vC0b, vC1b, vD0b, vD1b,
                                  wbP * uxb, wbP * wxb, wbQ * uxb, wbQ * wxb);

        outp[px * 128] = max4(max4(s_aa, s_ab), max4(s_ba, s_bb));
    }
}

// One block per (pooled_row, roi). 128 threads x float4 = 512 channels.
// Row-tap dedup via ONE block-uniform dispatch; cell loop is branch-free.
// min-blocks 12 caps regs at ~42 -> 48 resident warps/SM (vs 40 at regs=48)
// to convert latency exposure into L1 throughput.
__global__ __launch_bounds__(128, 12) void roi_pool_kernel(
    const float* __restrict__ fm,     // [38,50,512]
    const float* __restrict__ rois,   // [512,5] (0, x1, y1, x2, y2)
    float* __restrict__ out)          // [512,7,7,512]
{
    const int py  = blockIdx.x;       // 0..6
    const int roi = blockIdx.y;       // 0..511
    const int t   = threadIdx.x;      // channel group: c = 4*t

    const float* r = rois + roi * 5;
    const float x1n = r[1] * (1.0f / 800.0f);
    const float y1n = r[2] * (1.0f / 600.0f);
    const float x2n = r[3] * (1.0f / 800.0f);
    const float y2n = r[4] * (1.0f / 600.0f);
    const float dy = y2n - y1n;
    const float dx = x2n - x1n;

    // y taps for the two crop rows of this pooled row (block-uniform)
    int ra0, ra1, rb0, rb1;           // fm row offsets (row * FM_W)
    float wya, wyb;
    {
        const float tya = (float)(2 * py) * (1.0f / 13.0f);
        const float ysa = (y1n + tya * dy) * (float)(FM_H - 1);
        const float yfa = floorf(ysa);
        int y0 = (int)yfa; y0 = min(max(y0, 0), FM_H - 1);
        ra0 = y0 * FM_W;
        ra1 = min(y0 + 1, FM_H - 1) * FM_W;
        wya = ysa - yfa;

        const float tyb = (float)(2 * py + 1) * (1.0f / 13.0f);
        const float ysb = (y1n + tyb * dy) * (float)(FM_H - 1);
        const float yfb = floorf(ysb);
        int y1 = (int)yfb; y1 = min(max(y1, 0), FM_H - 1);
        rb0 = y1 * FM_W;
        rb1 = min(y1 + 1, FM_H - 1) * FM_W;
        wyb = ysb - yfb;
    }
    const float uya = 1.0f - wya;
    const float uyb = 1.0f - wyb;

    const float4* fmt = (const float4*)fm + t;
    float4* outp = (float4*)out + (size_t)((roi * POOL + py) * POOL) * 128 + t;

    // Row dedup dispatch (block-uniform branch, fixed for all 7 cells).
    if (rb0 == ra0) {
        run_row<0>(fmt, outp, x1n, dx, ra0, ra1, 0, 0,
                   uya, wya, uyb, wyb);
    } else if (rb0 == ra1) {
        if (rb1 == rb0) {
            run_row<0>(fmt, outp, x1n, dx, ra0, ra1, 0, 0,
                       uya, wya, 0.0f, uyb + wyb);
        } else {
            run_row<1>(fmt, outp, x1n, dx, ra0, ra1, rb1, 0,
                       uya, wya, uyb, wyb);
        }
    } else {
        run_row<2>(fmt, outp, x1n, dx, ra0, ra1, rb0, rb1,
                   uya, wya, uyb, wyb);
    }
}

extern "C" void kernel_launch(void* const* d_in, const int* in_sizes, int n_in,
                              void* d_out, int out_size)
{
    const float* fm   = (const float*)d_in[0];   // feature_maps [1,38,50,512]
    const float* rois = (const float*)d_in[1];   // [512,5]
    float* out = (float*)d_out;                  // [1,512,7,7,512]

    dim3 grid(POOL, N_ROI);
    roi_pool_kernel<<<grid, 128>>>(fm, rois, out);
}